// round 6
// baseline (speedup 1.0000x reference)
#include <cuda_runtime.h>
#include <math.h>

#define T_STEPS 400
#define BATCH   128
#define HID     512
#define OC      64

typedef unsigned long long ull;

// ---------------- device scratch ----------------
__device__ __align__(16) float g_ybuf[OC * T_STEPS * BATCH];   // [oc][t][b]
__device__ __align__(16) float g_seq [T_STEPS * OC * BATCH];   // [t][c][b]
__device__ float g_scale[OC];
__device__ float g_shift[OC];
__device__ __align__(16) float g_memL[OC * BATCH];
__device__ __align__(16) float g_S1[576 * BATCH];     // rows 0-63 spikes, 64-575 mem1
__device__ __align__(16) float g_S2[1024 * BATCH];    // rows 0-511 spk1, 512-1023 mem2
__device__ __align__(16) float g_syn1[HID * BATCH];
__device__ __align__(16) float g_syn2[HID * BATCH];
__device__ __align__(16) float g_acc2[HID * BATCH];
__device__ __align__(16) float g_part[8 * 2048 * BATCH];  // split-K partials
__device__ unsigned g_bar_count;
__device__ unsigned g_bar_phase;

// ---------------- helpers ----------------
__device__ __forceinline__ float sigf(float x) { return 1.f / (1.f + expf(-x)); }
__device__ __forceinline__ ull packf2(float w) {
    ull r; unsigned u = __float_as_uint(w);
    asm("mov.b64 %0, {%1, %1};" : "=l"(r) : "r"(u));
    return r;
}
__device__ __forceinline__ void fma2(ull& acc, ull a, ull b) {
    asm("fma.rn.f32x2 %0, %1, %2, %0;" : "+l"(acc) : "l"(a), "l"(b));
}
__device__ __forceinline__ void cpa16cg(void* dst_smem, const void* src) {
    unsigned d = (unsigned)__cvta_generic_to_shared(dst_smem);
    asm volatile("cp.async.cg.shared.global [%0], [%1], 16;" :: "r"(d), "l"(src));
}
#define CP_COMMIT() asm volatile("cp.async.commit_group;" ::: "memory")

__device__ __forceinline__ void grid_barrier() {
    __syncthreads();
    if (threadIdx.x == 0) {
        unsigned ph;
        asm volatile("ld.relaxed.gpu.u32 %0, [%1];" : "=r"(ph) : "l"(&g_bar_phase));
        unsigned old;
        asm volatile("atom.add.release.gpu.u32 %0, [%1], %2;"
                     : "=r"(old) : "l"(&g_bar_count), "r"(1u) : "memory");
        if (old == gridDim.x - 1) {
            asm volatile("st.relaxed.gpu.u32 [%0], %1;" :: "l"(&g_bar_count), "r"(0u) : "memory");
            asm volatile("st.release.gpu.u32 [%0], %1;" :: "l"(&g_bar_phase), "r"(ph + 1) : "memory");
        } else {
            unsigned cur;
            do {
                asm volatile("ld.acquire.gpu.u32 %0, [%1];" : "=r"(cur) : "l"(&g_bar_phase));
            } while (cur == ph);
        }
    }
    __syncthreads();
}

// ---------------- conv1d (pad=2, k=5): block=t, threads=b ----------------
__global__ void conv_kernel(const float* __restrict__ x, const float* __restrict__ w) {
    __shared__ float s_w[OC * 70];
    int t = blockIdx.x, b = threadIdx.x;
    for (int i = b; i < OC * 70; i += 128) s_w[i] = w[i];
    float xr[5][14];
#pragma unroll
    for (int k = 0; k < 5; k++) {
        int tt = t + k - 2;
        bool ok = (tt >= 0 && tt < T_STEPS);
#pragma unroll
        for (int c = 0; c < 14; c++)
            xr[k][c] = ok ? x[(tt * BATCH + b) * 14 + c] : 0.f;
    }
    __syncthreads();
    for (int oc = 0; oc < OC; oc++) {
        float acc = 0.f;
        const float* wr = s_w + oc * 70;
#pragma unroll
        for (int c = 0; c < 14; c++)
#pragma unroll
            for (int k = 0; k < 5; k++)
                acc = fmaf(xr[k][c], wr[c * 5 + k], acc);
        g_ybuf[oc * (T_STEPS * BATCH) + t * BATCH + b] = acc;
    }
}

__global__ void stats_kernel(const float* __restrict__ bn_g, const float* __restrict__ bn_b) {
    int c = blockIdx.x;
    const float* base = g_ybuf + c * (T_STEPS * BATCH);
    double s = 0.0, sq = 0.0;
    for (int i = threadIdx.x; i < T_STEPS * BATCH; i += 256) {
        float v = base[i];
        s += v; sq += (double)v * (double)v;
    }
    __shared__ double rs[256], rq[256];
    rs[threadIdx.x] = s; rq[threadIdx.x] = sq;
    __syncthreads();
    for (int st = 128; st > 0; st >>= 1) {
        if (threadIdx.x < st) { rs[threadIdx.x] += rs[threadIdx.x + st]; rq[threadIdx.x] += rq[threadIdx.x + st]; }
        __syncthreads();
    }
    if (threadIdx.x == 0) {
        double n = (double)(T_STEPS * BATCH);
        double mu = rs[0] / n;
        double var = rq[0] / n - mu * mu;
        float sc = bn_g[c] * (float)(1.0 / sqrt(var + 1e-5));
        g_scale[c] = sc;
        g_shift[c] = bn_b[c] - (float)mu * sc;
    }
}

__global__ void norm_kernel() {
    int i = blockIdx.x * 256 + threadIdx.x;
    if (i >= OC * T_STEPS * BATCH) return;
    int oc = i / (T_STEPS * BATCH);
    int rem = i % (T_STEPS * BATCH);
    int t = rem / BATCH, b = rem % BATCH;
    g_seq[t * (OC * BATCH) + oc * BATCH + b] = g_ybuf[i] * g_scale[oc] + g_shift[oc];
}

// ---------------- persistent scan kernel ----------------
// grid 128 = 16 gate-tiles x 8 k-splits; 512 threads; thread tile 4 gates x 8 batch
// smem: w1 dup [72][128] ull + w2 dup [128][128] ull + state ring 4 x 8 x 128 f32

template <int KS>
__device__ __forceinline__ void gemm_phase(const float* __restrict__ gstate,
                                           const ull* __restrict__ wd,
                                           float* __restrict__ spart,
                                           float* __restrict__ sbuf,
                                           int gg, int bgr)
{
    const int NCHK = KS / 8;
    const int tid = threadIdx.x;

    auto fetch = [&](int c) {
        if (c < NCHK && tid < 256)
            cpa16cg(sbuf + ((c & 3) << 10) + tid * 4, gstate + (c << 10) + tid * 4);
        CP_COMMIT();
    };
    fetch(0); fetch(1); fetch(2);

    ull acc[4][4];
#pragma unroll
    for (int j = 0; j < 4; j++)
#pragma unroll
        for (int q = 0; q < 4; q++) acc[j][q] = 0ull;

    for (int c = 0; c < NCHK; c++) {
        asm volatile("cp.async.wait_group 2;" ::: "memory");
        __syncthreads();
        fetch(c + 3);
        const float* sb = sbuf + ((c & 3) << 10) + bgr * 8;
        const ull* wb = wd + c * 1024 + gg * 4;
#pragma unroll
        for (int kk = 0; kk < 8; kk++) {
            ulonglong2 s01 = *(const ulonglong2*)(sb + kk * 128);
            ulonglong2 s23 = *(const ulonglong2*)(sb + kk * 128 + 4);
            ulonglong2 wA = *(const ulonglong2*)(wb + kk * 128);
            ulonglong2 wB = *(const ulonglong2*)(wb + kk * 128 + 2);
            fma2(acc[0][0], s01.x, wA.x); fma2(acc[0][1], s01.y, wA.x);
            fma2(acc[0][2], s23.x, wA.x); fma2(acc[0][3], s23.y, wA.x);
            fma2(acc[1][0], s01.x, wA.y); fma2(acc[1][1], s01.y, wA.y);
            fma2(acc[1][2], s23.x, wA.y); fma2(acc[1][3], s23.y, wA.y);
            fma2(acc[2][0], s01.x, wB.x); fma2(acc[2][1], s01.y, wB.x);
            fma2(acc[2][2], s23.x, wB.x); fma2(acc[2][3], s23.y, wB.x);
            fma2(acc[3][0], s01.x, wB.y); fma2(acc[3][1], s01.y, wB.y);
            fma2(acc[3][2], s23.x, wB.y); fma2(acc[3][3], s23.y, wB.y);
        }
    }

    // write partials: rows gg*4+j, cols bgr*8..+8
#pragma unroll
    for (int j = 0; j < 4; j++) {
        float* dst = spart + (gg * 4 + j) * 128 + bgr * 8;
        ulonglong2 v0, v1;
        v0.x = acc[j][0]; v0.y = acc[j][1];
        v1.x = acc[j][2]; v1.y = acc[j][3];
        *(ulonglong2*)dst = v0;
        *(ulonglong2*)(dst + 4) = v1;
    }
}

__device__ __forceinline__ void epi_slstm(int layer, float thr,
                                          const float* __restrict__ bi,
                                          const float* __restrict__ bh) {
    int e = blockIdx.x * 512 + threadIdx.x;   // [0, 65536)
    int h = e >> 7, b = e & 127;
    float sums[4];
#pragma unroll
    for (int gt = 0; gt < 4; gt++) {
        int r = gt * 512 + h;
        const float* pp = g_part + (r >> 7) * 16384 + (r & 127) * 128 + b;
        float s = 0.f;
#pragma unroll
        for (int sp = 0; sp < 8; sp++)
            s += __ldcg(pp + sp * 262144);
        sums[gt] = s + __ldg(bi + r) + __ldg(bh + r);
    }
    float* syn  = (layer == 1) ? g_syn1 : g_syn2;
    float* memr = (layer == 1) ? (g_S1 + 64 * 128) : (g_S2 + 512 * 128);
    float sv = syn[e];
    float mo = __ldcg(&memr[e]);
    float reset = (mo > thr) ? thr : 0.f;
    float sn = sigf(sums[1]) * sv + sigf(sums[0]) * tanhf(sums[2]);
    float mn = sigf(sums[3]) * tanhf(sn) - reset;
    syn[e] = sn;
    memr[e] = mn;
    if (layer == 1) g_S2[e] = (mn > thr) ? 1.f : 0.f;
    else g_acc2[e] += mn;
}

__device__ __forceinline__ void lif_phase(int t, float thrL) {
    if (threadIdx.x < 64) {
        int e = blockIdx.x * 64 + threadIdx.x;
        float mo = g_memL[e];
        float xt = g_seq[t * 8192 + e];
        float reset = (mo > thrL) ? thrL : 0.f;
        float mn = 0.9f * mo + xt - reset;
        g_memL[e] = mn;
        g_S1[e] = (mn > thrL) ? 1.f : 0.f;
    }
}

__global__ void __launch_bounds__(512, 1) scan_kernel(
    const float* __restrict__ w_ih1, const float* __restrict__ w_hh1,
    const float* __restrict__ b_ih1, const float* __restrict__ b_hh1,
    const float* __restrict__ w_ih2, const float* __restrict__ w_hh2,
    const float* __restrict__ b_ih2, const float* __restrict__ b_hh2,
    const float* __restrict__ thrL_p, const float* __restrict__ thr1_p,
    const float* __restrict__ thr2_p)
{
    extern __shared__ char smem[];
    ull*   w1d  = (ull*)smem;                  // 72*128 ull  = 73728 B
    ull*   w2d  = (ull*)(smem + 73728);        // 128*128 ull = 131072 B
    float* sbuf = (float*)(smem + 204800);     // 4 x 1024 f32 = 16384 B

    const int tid = threadIdx.x;
    const int cta = blockIdx.x;
    const int tile = cta >> 3, split = cta & 7;
    const int gg = tid >> 4, bgr = tid & 15;
    const float thrL = __ldg(thrL_p), thr1 = __ldg(thr1_p), thr2 = __ldg(thr2_p);
    const int gid = cta * 512 + tid;

    // ---- prologue: zero recurrent state (each launch) ----
    {
        int i = gid;                       // exactly 65536 threads
        g_S1[8192 + i] = 0.f;              // mem1
        g_S2[65536 + i] = 0.f;             // mem2
        g_syn1[i] = 0.f; g_syn2[i] = 0.f; g_acc2[i] = 0.f;
    }

    // ---- prologue: pack duplicated weights into resident smem [k][gate] ----
    for (int i = tid; i < 72 * 128; i += 512) {
        int kl = i >> 7, gi = i & 127;
        int r = tile * 128 + gi;
        int kg = split * 72 + kl;
        float w = (kg < 64) ? __ldg(w_ih1 + r * 64 + kg) : __ldg(w_hh1 + r * 512 + kg - 64);
        w1d[i] = packf2(w);
    }
    for (int i = tid; i < 128 * 128; i += 512) {
        int kl = i >> 7, gi = i & 127;
        int r = tile * 128 + gi;
        int kg = split * 128 + kl;
        float w = (kg < 512) ? __ldg(w_ih2 + r * 512 + kg) : __ldg(w_hh2 + r * 512 + kg - 512);
        w2d[i] = packf2(w);
    }

    // LIF at t=0: mem starts at 0, so mem_new = x_t exactly
    if (tid < 64) {
        int e = cta * 64 + tid;
        float xt = g_seq[e];
        g_memL[e] = xt;
        g_S1[e] = (xt > thrL) ? 1.f : 0.f;
    }
    grid_barrier();

    float* spart = g_part + split * 262144 + tile * 16384;

    for (int t = 0; t < T_STEPS; t++) {
        gemm_phase<72>(g_S1 + split * 9216, w1d, spart, sbuf, gg, bgr);
        grid_barrier();
        epi_slstm(1, thr1, b_ih1, b_hh1);
        grid_barrier();
        gemm_phase<128>(g_S2 + split * 16384, w2d, spart, sbuf, gg, bgr);
        grid_barrier();
        epi_slstm(2, thr2, b_ih2, b_hh2);
        if (t + 1 < T_STEPS) lif_phase(t + 1, thrL);
        grid_barrier();
    }
}

// ---------------- heads ----------------
__global__ void heads_kernel(const float* __restrict__ wg, const float* __restrict__ bg,
                             const float* __restrict__ wd1, const float* __restrict__ bd1,
                             const float* __restrict__ wd2, const float* __restrict__ bd2,
                             const float* __restrict__ thr_dom_p, float* __restrict__ out)
{
    __shared__ float feat[512];
    __shared__ float sd[64];
    int b = blockIdx.x, tid = threadIdx.x;
    const float thr = *thr_dom_p;
#pragma unroll
    for (int j = 0; j < 4; j++)
        feat[tid + j * 128] = g_acc2[(tid + j * 128) * 128 + b] * (1.f / 400.f);
    __syncthreads();
    if (tid < 8) {
        float acc = bg[tid];
        for (int h = 0; h < 512; h++) acc = fmaf(feat[h], wg[tid * 512 + h], acc);
        out[b * 8 + tid] = acc;
    }
    if (tid < 64) {
        float acc = bd1[tid];
        for (int h = 0; h < 512; h++) acc = fmaf(feat[h], wd1[tid * 512 + h], acc);
        sd[tid] = (acc - thr > 0.f) ? 1.f : 0.f;
    }
    __syncthreads();
    if (tid < 10) {
        float acc = bd2[tid];
        for (int k = 0; k < 64; k++) acc = fmaf(sd[k], wd2[tid * 64 + k], acc);
        out[128 * 8 + b * 10 + tid] = acc;
    }
}

extern "C" void kernel_launch(void* const* d_in, const int* in_sizes, int n_in,
                              void* d_out, int out_size) {
    const float* x       = (const float*)d_in[0];
    const float* conv_w  = (const float*)d_in[1];
    const float* bn_g    = (const float*)d_in[2];
    const float* bn_b    = (const float*)d_in[3];
    const float* w_ih1   = (const float*)d_in[4];
    const float* w_hh1   = (const float*)d_in[5];
    const float* b_ih1   = (const float*)d_in[6];
    const float* b_hh1   = (const float*)d_in[7];
    const float* w_ih2   = (const float*)d_in[8];
    const float* w_hh2   = (const float*)d_in[9];
    const float* b_ih2   = (const float*)d_in[10];
    const float* b_hh2   = (const float*)d_in[11];
    const float* wg      = (const float*)d_in[12];
    const float* bg      = (const float*)d_in[13];
    const float* wd1     = (const float*)d_in[14];
    const float* bd1     = (const float*)d_in[15];
    const float* wd2     = (const float*)d_in[16];
    const float* bd2     = (const float*)d_in[17];
    const float* thrL    = (const float*)d_in[18];
    const float* thr1    = (const float*)d_in[19];
    const float* thr2    = (const float*)d_in[20];
    const float* thrD    = (const float*)d_in[21];

    const int SMEM_SCAN = 73728 + 131072 + 16384;   // 221184 B
    cudaFuncSetAttribute(scan_kernel, cudaFuncAttributeMaxDynamicSharedMemorySize, SMEM_SCAN);

    conv_kernel<<<T_STEPS, 128>>>(x, conv_w);
    stats_kernel<<<OC, 256>>>(bn_g, bn_b);
    norm_kernel<<<(OC * T_STEPS * BATCH + 255) / 256, 256>>>();
    scan_kernel<<<128, 512, SMEM_SCAN>>>(w_ih1, w_hh1, b_ih1, b_hh1,
                                         w_ih2, w_hh2, b_ih2, b_hh2,
                                         thrL, thr1, thr2);
    heads_kernel<<<128, 128>>>(wg, bg, wd1, bd1, wd2, bd2, thrD, (float*)d_out);
}

// round 7
// speedup vs baseline: 1.1759x; 1.1759x over previous
#include <cuda_runtime.h>
#include <math.h>

#define T_STEPS 400
#define BATCH   128
#define HID     512
#define OC      64
#define NSPLIT  16
#define K1S     36     // 576/16
#define K2S     64     // 1024/16

typedef unsigned long long ull;

// ---------------- device scratch ----------------
__device__ __align__(16) float g_ybuf[OC * T_STEPS * BATCH];   // [oc][t][b]
__device__ __align__(16) float g_seq [T_STEPS * OC * BATCH];   // [t][c][b]
__device__ float g_scale[OC];
__device__ float g_shift[OC];
__device__ __align__(16) float g_memL[OC * BATCH];
__device__ __align__(16) float g_S1[576 * BATCH];     // rows 0-63 spikes, 64-575 mem1
__device__ __align__(16) float g_S2[1024 * BATCH];    // rows 0-511 spk1, 512-1023 mem2
__device__ __align__(16) float g_syn1[HID * BATCH];
__device__ __align__(16) float g_syn2[HID * BATCH];
__device__ __align__(16) float g_acc2[HID * BATCH];
__device__ __align__(16) float g_partA[NSPLIT * 2048 * BATCH];  // gemm1 partials
__device__ __align__(16) float g_partB[NSPLIT * 2048 * BATCH];  // gemm2 partials
__device__ unsigned g_bar_count;
__device__ unsigned g_bar_phase;

// ---------------- helpers ----------------
__device__ __forceinline__ float sigf(float x) { return 1.f / (1.f + expf(-x)); }
__device__ __forceinline__ ull packf2(float w) {
    ull r; unsigned u = __float_as_uint(w);
    asm("mov.b64 %0, {%1, %1};" : "=l"(r) : "r"(u));
    return r;
}
__device__ __forceinline__ void fma2(ull& acc, ull a, ull b) {
    asm("fma.rn.f32x2 %0, %1, %2, %0;" : "+l"(acc) : "l"(a), "l"(b));
}
__device__ __forceinline__ void cpa16cg(void* dst_smem, const void* src) {
    unsigned d = (unsigned)__cvta_generic_to_shared(dst_smem);
    asm volatile("cp.async.cg.shared.global [%0], [%1], 16;" :: "r"(d), "l"(src));
}
#define CP_COMMIT() asm volatile("cp.async.commit_group;" ::: "memory")

__device__ __forceinline__ void grid_barrier() {
    __syncthreads();
    if (threadIdx.x == 0) {
        unsigned ph;
        asm volatile("ld.relaxed.gpu.u32 %0, [%1];" : "=r"(ph) : "l"(&g_bar_phase));
        unsigned old;
        asm volatile("atom.add.release.gpu.u32 %0, [%1], %2;"
                     : "=r"(old) : "l"(&g_bar_count), "r"(1u) : "memory");
        if (old == gridDim.x - 1) {
            asm volatile("st.relaxed.gpu.u32 [%0], %1;" :: "l"(&g_bar_count), "r"(0u) : "memory");
            asm volatile("st.release.gpu.u32 [%0], %1;" :: "l"(&g_bar_phase), "r"(ph + 1) : "memory");
        } else {
            unsigned cur;
            do {
                asm volatile("ld.acquire.gpu.u32 %0, [%1];" : "=r"(cur) : "l"(&g_bar_phase));
            } while (cur == ph);
        }
    }
    __syncthreads();
}

// ---------------- conv1d (pad=2, k=5): block=t, threads=b ----------------
__global__ void conv_kernel(const float* __restrict__ x, const float* __restrict__ w) {
    __shared__ float s_w[OC * 70];
    int t = blockIdx.x, b = threadIdx.x;
    for (int i = b; i < OC * 70; i += 128) s_w[i] = w[i];
    float xr[5][14];
#pragma unroll
    for (int k = 0; k < 5; k++) {
        int tt = t + k - 2;
        bool ok = (tt >= 0 && tt < T_STEPS);
#pragma unroll
        for (int c = 0; c < 14; c++)
            xr[k][c] = ok ? x[(tt * BATCH + b) * 14 + c] : 0.f;
    }
    __syncthreads();
    for (int oc = 0; oc < OC; oc++) {
        float acc = 0.f;
        const float* wr = s_w + oc * 70;
#pragma unroll
        for (int c = 0; c < 14; c++)
#pragma unroll
            for (int k = 0; k < 5; k++)
                acc = fmaf(xr[k][c], wr[c * 5 + k], acc);
        g_ybuf[oc * (T_STEPS * BATCH) + t * BATCH + b] = acc;
    }
}

__global__ void stats_kernel(const float* __restrict__ bn_g, const float* __restrict__ bn_b) {
    int c = blockIdx.x;
    const float* base = g_ybuf + c * (T_STEPS * BATCH);
    double s = 0.0, sq = 0.0;
    for (int i = threadIdx.x; i < T_STEPS * BATCH; i += 256) {
        float v = base[i];
        s += v; sq += (double)v * (double)v;
    }
    __shared__ double rs[256], rq[256];
    rs[threadIdx.x] = s; rq[threadIdx.x] = sq;
    __syncthreads();
    for (int st = 128; st > 0; st >>= 1) {
        if (threadIdx.x < st) { rs[threadIdx.x] += rs[threadIdx.x + st]; rq[threadIdx.x] += rq[threadIdx.x + st]; }
        __syncthreads();
    }
    if (threadIdx.x == 0) {
        double n = (double)(T_STEPS * BATCH);
        double mu = rs[0] / n;
        double var = rq[0] / n - mu * mu;
        float sc = bn_g[c] * (float)(1.0 / sqrt(var + 1e-5));
        g_scale[c] = sc;
        g_shift[c] = bn_b[c] - (float)mu * sc;
    }
}

__global__ void norm_kernel() {
    int i = blockIdx.x * 256 + threadIdx.x;
    if (i >= OC * T_STEPS * BATCH) return;
    int oc = i / (T_STEPS * BATCH);
    int rem = i % (T_STEPS * BATCH);
    int t = rem / BATCH, b = rem % BATCH;
    g_seq[t * (OC * BATCH) + oc * BATCH + b] = g_ybuf[i] * g_scale[oc] + g_shift[oc];
}

// ---------------- persistent scan kernel ----------------
// grid 128 = 8 gate-tiles(256 rows) x 16 k-splits; 512 threads
// warp owns 16 gate rows (broadcast weights), lane owns 4 batch
// smem: w1 dup [36][256] ull + w2 dup [64][256] ull + state ring 4 x 4k x 128 f32

template <int KSPLIT>
__device__ __forceinline__ void gemm_phase(const float* __restrict__ gstate,
                                           const ull* __restrict__ wd,
                                           float* __restrict__ spart,
                                           float* __restrict__ sbuf,
                                           int warp, int lane)
{
    const int NCHK = KSPLIT / 4;
    const int tid = threadIdx.x;

    auto fetch = [&](int c) {
        if (c < NCHK && tid < 128)
            cpa16cg(sbuf + ((c & 3) << 9) + tid * 4, gstate + (c << 9) + tid * 4);
        CP_COMMIT();
    };
    fetch(0); fetch(1); fetch(2);

    ull acc[16][2];
#pragma unroll
    for (int j = 0; j < 16; j++) { acc[j][0] = 0ull; acc[j][1] = 0ull; }

    for (int c = 0; c < NCHK; c++) {
        asm volatile("cp.async.wait_group 2;" ::: "memory");
        __syncthreads();
        fetch(c + 3);
        const float* sb = sbuf + ((c & 3) << 9) + lane * 4;
        const ull* wb = wd + (c << 10) + warp * 16;
#pragma unroll
        for (int kk = 0; kk < 4; kk++) {
            ulonglong2 sv = *(const ulonglong2*)(sb + (kk << 7));
            const ull* wk = wb + (kk << 8);
            {
                ulonglong2 w01 = *(const ulonglong2*)(wk);
                ulonglong2 w23 = *(const ulonglong2*)(wk + 2);
                ulonglong2 w45 = *(const ulonglong2*)(wk + 4);
                ulonglong2 w67 = *(const ulonglong2*)(wk + 6);
                fma2(acc[0][0], sv.x, w01.x); fma2(acc[0][1], sv.y, w01.x);
                fma2(acc[1][0], sv.x, w01.y); fma2(acc[1][1], sv.y, w01.y);
                fma2(acc[2][0], sv.x, w23.x); fma2(acc[2][1], sv.y, w23.x);
                fma2(acc[3][0], sv.x, w23.y); fma2(acc[3][1], sv.y, w23.y);
                fma2(acc[4][0], sv.x, w45.x); fma2(acc[4][1], sv.y, w45.x);
                fma2(acc[5][0], sv.x, w45.y); fma2(acc[5][1], sv.y, w45.y);
                fma2(acc[6][0], sv.x, w67.x); fma2(acc[6][1], sv.y, w67.x);
                fma2(acc[7][0], sv.x, w67.y); fma2(acc[7][1], sv.y, w67.y);
            }
            {
                ulonglong2 w89 = *(const ulonglong2*)(wk + 8);
                ulonglong2 wab = *(const ulonglong2*)(wk + 10);
                ulonglong2 wcd = *(const ulonglong2*)(wk + 12);
                ulonglong2 wef = *(const ulonglong2*)(wk + 14);
                fma2(acc[8][0],  sv.x, w89.x); fma2(acc[8][1],  sv.y, w89.x);
                fma2(acc[9][0],  sv.x, w89.y); fma2(acc[9][1],  sv.y, w89.y);
                fma2(acc[10][0], sv.x, wab.x); fma2(acc[10][1], sv.y, wab.x);
                fma2(acc[11][0], sv.x, wab.y); fma2(acc[11][1], sv.y, wab.y);
                fma2(acc[12][0], sv.x, wcd.x); fma2(acc[12][1], sv.y, wcd.x);
                fma2(acc[13][0], sv.x, wcd.y); fma2(acc[13][1], sv.y, wcd.y);
                fma2(acc[14][0], sv.x, wef.x); fma2(acc[14][1], sv.y, wef.x);
                fma2(acc[15][0], sv.x, wef.y); fma2(acc[15][1], sv.y, wef.y);
            }
        }
    }

    // write partials: rows warp*16+j, cols lane*4..+4
#pragma unroll
    for (int j = 0; j < 16; j++) {
        ulonglong2 v; v.x = acc[j][0]; v.y = acc[j][1];
        *(ulonglong2*)(spart + (warp * 16 + j) * 128 + lane * 4) = v;
    }
}

__device__ __forceinline__ void epi_slstm(int layer, float thr,
                                          const float* __restrict__ part,
                                          const float* __restrict__ bi,
                                          const float* __restrict__ bh) {
    int e = blockIdx.x * 512 + threadIdx.x;   // [0, 65536)
    int h = e >> 7, b = e & 127;
    float sums[4];
#pragma unroll
    for (int gt = 0; gt < 4; gt++) {
        int r = gt * 512 + h;
        const float* pp = part + (r >> 8) * 32768 + (r & 255) * 128 + b;
        float s = 0.f;
#pragma unroll
        for (int sp = 0; sp < NSPLIT; sp++)
            s += __ldcg(pp + sp * (2048 * 128));
        sums[gt] = s + __ldg(bi + r) + __ldg(bh + r);
    }
    float* syn  = (layer == 1) ? g_syn1 : g_syn2;
    float* memr = (layer == 1) ? (g_S1 + 64 * 128) : (g_S2 + 512 * 128);
    float sv = syn[e];
    float mo = memr[e];
    float reset = (mo > thr) ? thr : 0.f;
    float sn = sigf(sums[1]) * sv + sigf(sums[0]) * tanhf(sums[2]);
    float mn = sigf(sums[3]) * tanhf(sn) - reset;
    syn[e] = sn;
    memr[e] = mn;
    if (layer == 1) g_S2[e] = (mn > thr) ? 1.f : 0.f;
    else g_acc2[e] += mn;
}

__device__ __forceinline__ void lif_phase(int t, float thrL) {
    if (threadIdx.x < 64) {
        int e = blockIdx.x * 64 + threadIdx.x;
        float mo = g_memL[e];
        float xt = g_seq[t * 8192 + e];
        float reset = (mo > thrL) ? thrL : 0.f;
        float mn = 0.9f * mo + xt - reset;
        g_memL[e] = mn;
        g_S1[e] = (mn > thrL) ? 1.f : 0.f;
    }
}

__global__ void __launch_bounds__(512, 1) scan_kernel(
    const float* __restrict__ w_ih1, const float* __restrict__ w_hh1,
    const float* __restrict__ b_ih1, const float* __restrict__ b_hh1,
    const float* __restrict__ w_ih2, const float* __restrict__ w_hh2,
    const float* __restrict__ b_ih2, const float* __restrict__ b_hh2,
    const float* __restrict__ thrL_p, const float* __restrict__ thr1_p,
    const float* __restrict__ thr2_p)
{
    extern __shared__ char smem[];
    ull*   w1d  = (ull*)smem;                  // 36*256 ull  = 73728 B
    ull*   w2d  = (ull*)(smem + 73728);        // 64*256 ull  = 131072 B
    float* sbuf = (float*)(smem + 204800);     // 4 x 512 f32 = 8192 B

    const int tid = threadIdx.x;
    const int cta = blockIdx.x;
    const int tile = cta >> 4, split = cta & 15;     // 8 tiles x 16 splits
    const int warp = tid >> 5, lane = tid & 31;
    const float thrL = __ldg(thrL_p), thr1 = __ldg(thr1_p), thr2 = __ldg(thr2_p);
    const int gid = cta * 512 + tid;

    // ---- prologue: zero recurrent state (each launch) ----
    {
        int i = gid;                       // exactly 65536 threads
        g_S1[8192 + i] = 0.f;              // mem1
        g_S2[65536 + i] = 0.f;             // mem2
        g_syn1[i] = 0.f; g_syn2[i] = 0.f; g_acc2[i] = 0.f;
    }

    // ---- prologue: pack duplicated weights into resident smem [k][gate] ----
    for (int i = tid; i < K1S * 256; i += 512) {
        int kl = i >> 8, g = i & 255;
        int r = tile * 256 + g;
        int kg = split * K1S + kl;
        float w = (kg < 64) ? __ldg(w_ih1 + r * 64 + kg) : __ldg(w_hh1 + r * 512 + kg - 64);
        w1d[i] = packf2(w);
    }
    for (int i = tid; i < K2S * 256; i += 512) {
        int kl = i >> 8, g = i & 255;
        int r = tile * 256 + g;
        int kg = split * K2S + kl;
        float w = (kg < 512) ? __ldg(w_ih2 + r * 512 + kg) : __ldg(w_hh2 + r * 512 + kg - 512);
        w2d[i] = packf2(w);
    }

    // LIF at t=0: mem starts at 0, so mem_new = x_t exactly
    if (tid < 64) {
        int e = cta * 64 + tid;
        float xt = g_seq[e];
        g_memL[e] = xt;
        g_S1[e] = (xt > thrL) ? 1.f : 0.f;
    }
    grid_barrier();

    float* spartA = g_partA + split * (2048 * 128) + tile * 32768;
    float* spartB = g_partB + split * (2048 * 128) + tile * 32768;

    for (int t = 0; t < T_STEPS; t++) {
        gemm_phase<K1S>(g_S1 + split * (K1S * 128), w1d, spartA, sbuf, warp, lane);
        grid_barrier();
        epi_slstm(1, thr1, g_partA, b_ih1, b_hh1);
        if (t + 1 < T_STEPS) lif_phase(t + 1, thrL);
        grid_barrier();
        gemm_phase<K2S>(g_S2 + split * (K2S * 128), w2d, spartB, sbuf, warp, lane);
        grid_barrier();
        epi_slstm(2, thr2, g_partB, b_ih2, b_hh2);
        // no barrier: next gemm1 writes partA (epi1 already consumed), reads
        // S1 written before the epi1 barrier; epi2's mem2 writes are fenced
        // by the two barriers before the next gemm2.
    }
}

// ---------------- heads ----------------
__global__ void heads_kernel(const float* __restrict__ wg, const float* __restrict__ bg,
                             const float* __restrict__ wd1, const float* __restrict__ bd1,
                             const float* __restrict__ wd2, const float* __restrict__ bd2,
                             const float* __restrict__ thr_dom_p, float* __restrict__ out)
{
    __shared__ float feat[512];
    __shared__ float sd[64];
    int b = blockIdx.x, tid = threadIdx.x;
    const float thr = *thr_dom_p;
#pragma unroll
    for (int j = 0; j < 4; j++)
        feat[tid + j * 128] = g_acc2[(tid + j * 128) * 128 + b] * (1.f / 400.f);
    __syncthreads();
    if (tid < 8) {
        float acc = bg[tid];
        for (int h = 0; h < 512; h++) acc = fmaf(feat[h], wg[tid * 512 + h], acc);
        out[b * 8 + tid] = acc;
    }
    if (tid < 64) {
        float acc = bd1[tid];
        for (int h = 0; h < 512; h++) acc = fmaf(feat[h], wd1[tid * 512 + h], acc);
        sd[tid] = (acc - thr > 0.f) ? 1.f : 0.f;
    }
    __syncthreads();
    if (tid < 10) {
        float acc = bd2[tid];
        for (int k = 0; k < 64; k++) acc = fmaf(sd[k], wd2[tid * 64 + k], acc);
        out[128 * 8 + b * 10 + tid] = acc;
    }
}

extern "C" void kernel_launch(void* const* d_in, const int* in_sizes, int n_in,
                              void* d_out, int out_size) {
    const float* x       = (const float*)d_in[0];
    const float* conv_w  = (const float*)d_in[1];
    const float* bn_g    = (const float*)d_in[2];
    const float* bn_b    = (const float*)d_in[3];
    const float* w_ih1   = (const float*)d_in[4];
    const float* w_hh1   = (const float*)d_in[5];
    const float* b_ih1   = (const float*)d_in[6];
    const float* b_hh1   = (const float*)d_in[7];
    const float* w_ih2   = (const float*)d_in[8];
    const float* w_hh2   = (const float*)d_in[9];
    const float* b_ih2   = (const float*)d_in[10];
    const float* b_hh2   = (const float*)d_in[11];
    const float* wg      = (const float*)d_in[12];
    const float* bg      = (const float*)d_in[13];
    const float* wd1     = (const float*)d_in[14];
    const float* bd1     = (const float*)d_in[15];
    const float* wd2     = (const float*)d_in[16];
    const float* bd2     = (const float*)d_in[17];
    const float* thrL    = (const float*)d_in[18];
    const float* thr1    = (const float*)d_in[19];
    const float* thr2    = (const float*)d_in[20];
    const float* thrD    = (const float*)d_in[21];

    const int SMEM_SCAN = 73728 + 131072 + 8192;   // 212992 B
    cudaFuncSetAttribute(scan_kernel, cudaFuncAttributeMaxDynamicSharedMemorySize, SMEM_SCAN);

    conv_kernel<<<T_STEPS, 128>>>(x, conv_w);
    stats_kernel<<<OC, 256>>>(bn_g, bn_b);
    norm_kernel<<<(OC * T_STEPS * BATCH + 255) / 256, 256>>>();
    scan_kernel<<<128, 512, SMEM_SCAN>>>(w_ih1, w_hh1, b_ih1, b_hh1,
                                         w_ih2, w_hh2, b_ih2, b_hh2,
                                         thrL, thr1, thr2);
    heads_kernel<<<128, 128>>>(wg, bg, wd1, bd1, wd2, bd2, thrD, (float*)d_out);
}

// round 8
// speedup vs baseline: 1.3403x; 1.1398x over previous
#include <cuda_runtime.h>
#include <math.h>

#define T_STEPS 400
#define BATCH   128
#define HID     512
#define OC      64
#define NSPLIT  8
#define K1S     72     // 576/8
#define K2S     128    // 1024/8

typedef unsigned long long ull;

// ---------------- device scratch ----------------
__device__ __align__(16) float g_ybuf[OC * T_STEPS * BATCH];   // [oc][t][b]
__device__ __align__(16) float g_seq [T_STEPS * OC * BATCH];   // [t][c][b]
__device__ float g_scale[OC];
__device__ float g_shift[OC];
__device__ __align__(16) float g_memL[OC * BATCH];
__device__ __align__(16) float g_S1[576 * BATCH];     // rows 0-63 spikes, 64-575 mem1
__device__ __align__(16) float g_S2[1024 * BATCH];    // rows 0-511 spk1, 512-1023 mem2
__device__ __align__(16) float g_syn1[HID * BATCH];
__device__ __align__(16) float g_syn2[HID * BATCH];
__device__ __align__(16) float g_acc2[HID * BATCH];
__device__ __align__(16) float g_partA[NSPLIT * 2048 * BATCH];  // gemm1 partials
__device__ __align__(16) float g_partB[NSPLIT * 2048 * BATCH];  // gemm2 partials
__device__ unsigned g_flags[128];   // per-CTA barrier flags (monotonic)
__device__ unsigned g_phase;        // master-published phase (monotonic)

// ---------------- helpers ----------------
__device__ __forceinline__ float sigf(float x) { return 1.f / (1.f + expf(-x)); }
__device__ __forceinline__ ull packf2(float w) {
    ull r; unsigned u = __float_as_uint(w);
    asm("mov.b64 %0, {%1, %1};" : "=l"(r) : "r"(u));
    return r;
}
__device__ __forceinline__ void fma2(ull& acc, ull a, ull b) {
    asm("fma.rn.f32x2 %0, %1, %2, %0;" : "+l"(acc) : "l"(a), "l"(b));
}
__device__ __forceinline__ void cpa16cg(void* dst_smem, const void* src) {
    unsigned d = (unsigned)__cvta_generic_to_shared(dst_smem);
    asm volatile("cp.async.cg.shared.global [%0], [%1], 16;" :: "r"(d), "l"(src));
}
#define CP_COMMIT() asm volatile("cp.async.commit_group;" ::: "memory")

// flag-array grid barrier: each CTA posts its own slot; CTA 0 aggregates and
// publishes g_phase. Phase values are monotonic across graph replays (base is
// re-read from this CTA's OWN flag at kernel start — written only by itself,
// so no cross-CTA race at launch).
__device__ __forceinline__ void grid_barrier(unsigned ph) {
    __syncthreads();
    if (threadIdx.x == 0)
        asm volatile("st.release.gpu.u32 [%0], %1;"
                     :: "l"(g_flags + blockIdx.x), "r"(ph) : "memory");
    if (blockIdx.x == 0) {
        if (threadIdx.x < 128) {
            unsigned v;
            do {
                asm volatile("ld.acquire.gpu.u32 %0, [%1];"
                             : "=r"(v) : "l"(g_flags + threadIdx.x));
            } while ((int)(v - ph) < 0);
        }
        __syncthreads();
        if (threadIdx.x == 0)
            asm volatile("st.release.gpu.u32 [%0], %1;"
                         :: "l"(&g_phase), "r"(ph) : "memory");
    } else if (threadIdx.x == 0) {
        unsigned v;
        do {
            asm volatile("ld.acquire.gpu.u32 %0, [%1];" : "=r"(v) : "l"(&g_phase));
        } while ((int)(v - ph) < 0);
    }
    __syncthreads();
}

// ---------------- conv1d (pad=2, k=5): block=t, threads=b ----------------
__global__ void conv_kernel(const float* __restrict__ x, const float* __restrict__ w) {
    __shared__ float s_w[OC * 70];
    int t = blockIdx.x, b = threadIdx.x;
    for (int i = b; i < OC * 70; i += 128) s_w[i] = w[i];
    float xr[5][14];
#pragma unroll
    for (int k = 0; k < 5; k++) {
        int tt = t + k - 2;
        bool ok = (tt >= 0 && tt < T_STEPS);
#pragma unroll
        for (int c = 0; c < 14; c++)
            xr[k][c] = ok ? x[(tt * BATCH + b) * 14 + c] : 0.f;
    }
    __syncthreads();
    for (int oc = 0; oc < OC; oc++) {
        float acc = 0.f;
        const float* wr = s_w + oc * 70;
#pragma unroll
        for (int c = 0; c < 14; c++)
#pragma unroll
            for (int k = 0; k < 5; k++)
                acc = fmaf(xr[k][c], wr[c * 5 + k], acc);
        g_ybuf[oc * (T_STEPS * BATCH) + t * BATCH + b] = acc;
    }
}

__global__ void stats_kernel(const float* __restrict__ bn_g, const float* __restrict__ bn_b) {
    int c = blockIdx.x;
    const float* base = g_ybuf + c * (T_STEPS * BATCH);
    double s = 0.0, sq = 0.0;
    for (int i = threadIdx.x; i < T_STEPS * BATCH; i += 256) {
        float v = base[i];
        s += v; sq += (double)v * (double)v;
    }
    __shared__ double rs[256], rq[256];
    rs[threadIdx.x] = s; rq[threadIdx.x] = sq;
    __syncthreads();
    for (int st = 128; st > 0; st >>= 1) {
        if (threadIdx.x < st) { rs[threadIdx.x] += rs[threadIdx.x + st]; rq[threadIdx.x] += rq[threadIdx.x + st]; }
        __syncthreads();
    }
    if (threadIdx.x == 0) {
        double n = (double)(T_STEPS * BATCH);
        double mu = rs[0] / n;
        double var = rq[0] / n - mu * mu;
        float sc = bn_g[c] * (float)(1.0 / sqrt(var + 1e-5));
        g_scale[c] = sc;
        g_shift[c] = bn_b[c] - (float)mu * sc;
    }
}

__global__ void norm_kernel() {
    int i = blockIdx.x * 256 + threadIdx.x;
    if (i >= OC * T_STEPS * BATCH) return;
    int oc = i / (T_STEPS * BATCH);
    int rem = i % (T_STEPS * BATCH);
    int t = rem / BATCH, b = rem % BATCH;
    g_seq[t * (OC * BATCH) + oc * BATCH + b] = g_ybuf[i] * g_scale[oc] + g_shift[oc];
}

// ---------------- persistent scan kernel ----------------
// grid 128 = 16 gate-tiles(128 rows) x 8 k-splits; 512 threads
// warp owns 8 gate rows (broadcast dup weights), lane owns 4 batch
// smem: w1 dup [72][128] ull + w2 dup [128][128] ull + state ring 4 x 1024 f32

template <int KSPLIT>
__device__ __forceinline__ void gemm_phase(const float* __restrict__ gstate,
                                           const ull* __restrict__ wd,
                                           float* __restrict__ spart,
                                           float* __restrict__ sbuf,
                                           int warp, int lane)
{
    const int NCHK = KSPLIT / 8;      // chunk = 8 k rows = 1024 floats = 4KB
    const int tid = threadIdx.x;

    auto fetch = [&](int c) {
        if (c < NCHK && tid < 256)
            cpa16cg(sbuf + ((c & 3) << 10) + tid * 4, gstate + (c << 10) + tid * 4);
        CP_COMMIT();
    };
    fetch(0); fetch(1); fetch(2);

    ull acc[8][2];
#pragma unroll
    for (int j = 0; j < 8; j++) { acc[j][0] = 0ull; acc[j][1] = 0ull; }

    for (int c = 0; c < NCHK; c++) {
        asm volatile("cp.async.wait_group 2;" ::: "memory");
        __syncthreads();
        fetch(c + 3);
        const float* sb = sbuf + ((c & 3) << 10) + lane * 4;
        const ull* wb = wd + (c << 10) + warp * 8;
#pragma unroll
        for (int kk = 0; kk < 8; kk++) {
            ulonglong2 sv = *(const ulonglong2*)(sb + (kk << 7));
            const ull* wk = wb + (kk << 7);
            ulonglong2 w01 = *(const ulonglong2*)(wk);
            ulonglong2 w23 = *(const ulonglong2*)(wk + 2);
            ulonglong2 w45 = *(const ulonglong2*)(wk + 4);
            ulonglong2 w67 = *(const ulonglong2*)(wk + 6);
            fma2(acc[0][0], sv.x, w01.x); fma2(acc[0][1], sv.y, w01.x);
            fma2(acc[1][0], sv.x, w01.y); fma2(acc[1][1], sv.y, w01.y);
            fma2(acc[2][0], sv.x, w23.x); fma2(acc[2][1], sv.y, w23.x);
            fma2(acc[3][0], sv.x, w23.y); fma2(acc[3][1], sv.y, w23.y);
            fma2(acc[4][0], sv.x, w45.x); fma2(acc[4][1], sv.y, w45.x);
            fma2(acc[5][0], sv.x, w45.y); fma2(acc[5][1], sv.y, w45.y);
            fma2(acc[6][0], sv.x, w67.x); fma2(acc[6][1], sv.y, w67.x);
            fma2(acc[7][0], sv.x, w67.y); fma2(acc[7][1], sv.y, w67.y);
        }
    }

    // write partials: rows warp*8+j, cols lane*4..+4
#pragma unroll
    for (int j = 0; j < 8; j++) {
        ulonglong2 v; v.x = acc[j][0]; v.y = acc[j][1];
        *(ulonglong2*)(spart + (warp * 8 + j) * 128 + lane * 4) = v;
    }
}

__device__ __forceinline__ void epi_slstm(int layer, float thr,
                                          const float* __restrict__ part,
                                          const float* __restrict__ bi,
                                          const float* __restrict__ bh) {
    int e = blockIdx.x * 512 + threadIdx.x;   // [0, 65536)
    int h = e >> 7, b = e & 127;
    float sums[4];
#pragma unroll
    for (int gt = 0; gt < 4; gt++) {
        int r = gt * 512 + h;
        const float* pp = part + (r >> 7) * 16384 + (r & 127) * 128 + b;
        float s = 0.f;
#pragma unroll
        for (int sp = 0; sp < NSPLIT; sp++)
            s += __ldcg(pp + sp * (2048 * 128));
        sums[gt] = s + __ldg(bi + r) + __ldg(bh + r);
    }
    float* syn  = (layer == 1) ? g_syn1 : g_syn2;
    float* memr = (layer == 1) ? (g_S1 + 64 * 128) : (g_S2 + 512 * 128);
    float sv = syn[e];
    float mo = memr[e];
    float reset = (mo > thr) ? thr : 0.f;
    float sn = sigf(sums[1]) * sv + sigf(sums[0]) * tanhf(sums[2]);
    float mn = sigf(sums[3]) * tanhf(sn) - reset;
    syn[e] = sn;
    memr[e] = mn;
    if (layer == 1) g_S2[e] = (mn > thr) ? 1.f : 0.f;
    else g_acc2[e] += mn;
}

__device__ __forceinline__ void lif_phase(int t, float thrL) {
    if (threadIdx.x < 64) {
        int e = blockIdx.x * 64 + threadIdx.x;
        float mo = g_memL[e];
        float xt = g_seq[t * 8192 + e];
        float reset = (mo > thrL) ? thrL : 0.f;
        float mn = 0.9f * mo + xt - reset;
        g_memL[e] = mn;
        g_S1[e] = (mn > thrL) ? 1.f : 0.f;
    }
}

__global__ void __launch_bounds__(512, 1) scan_kernel(
    const float* __restrict__ w_ih1, const float* __restrict__ w_hh1,
    const float* __restrict__ b_ih1, const float* __restrict__ b_hh1,
    const float* __restrict__ w_ih2, const float* __restrict__ w_hh2,
    const float* __restrict__ b_ih2, const float* __restrict__ b_hh2,
    const float* __restrict__ thrL_p, const float* __restrict__ thr1_p,
    const float* __restrict__ thr2_p)
{
    extern __shared__ char smem[];
    ull*   w1d  = (ull*)smem;                  // 72*128 ull  = 73728 B
    ull*   w2d  = (ull*)(smem + 73728);        // 128*128 ull = 131072 B
    float* sbuf = (float*)(smem + 204800);     // 4 x 1024 f32 = 16384 B

    const int tid = threadIdx.x;
    const int cta = blockIdx.x;
    const int tile = cta >> 3, split = cta & 7;     // 16 tiles x 8 splits
    const int warp = tid >> 5, lane = tid & 31;
    const float thrL = __ldg(thrL_p), thr1 = __ldg(thr1_p), thr2 = __ldg(thr2_p);
    const int gid = cta * 512 + tid;

    // phase base: this CTA's own flag (stable — only this CTA writes it)
    unsigned ph;
    asm volatile("ld.relaxed.gpu.u32 %0, [%1];" : "=r"(ph) : "l"(g_flags + cta));

    // ---- prologue: zero recurrent state (each launch) ----
    {
        int i = gid;                       // exactly 65536 threads
        g_S1[8192 + i] = 0.f;              // mem1
        g_S2[65536 + i] = 0.f;             // mem2
        g_syn1[i] = 0.f; g_syn2[i] = 0.f; g_acc2[i] = 0.f;
    }

    // ---- prologue: pack duplicated weights into resident smem [k][gate] ----
    for (int i = tid; i < K1S * 128; i += 512) {
        int kl = i >> 7, g = i & 127;
        int r = tile * 128 + g;
        int kg = split * K1S + kl;
        float w = (kg < 64) ? __ldg(w_ih1 + r * 64 + kg) : __ldg(w_hh1 + r * 512 + kg - 64);
        w1d[i] = packf2(w);
    }
    for (int i = tid; i < K2S * 128; i += 512) {
        int kl = i >> 7, g = i & 127;
        int r = tile * 128 + g;
        int kg = split * K2S + kl;
        float w = (kg < 512) ? __ldg(w_ih2 + r * 512 + kg) : __ldg(w_hh2 + r * 512 + kg - 512);
        w2d[i] = packf2(w);
    }

    // LIF at t=0: mem starts at 0, so mem_new = x_t exactly
    if (tid < 64) {
        int e = cta * 64 + tid;
        float xt = g_seq[e];
        g_memL[e] = xt;
        g_S1[e] = (xt > thrL) ? 1.f : 0.f;
    }
    ph++; grid_barrier(ph);

    float* spartA = g_partA + split * 262144 + tile * 16384;
    float* spartB = g_partB + split * 262144 + tile * 16384;

    for (int t = 0; t < T_STEPS; t++) {
        gemm_phase<K1S>(g_S1 + split * (K1S * 128), w1d, spartA, sbuf, warp, lane);
        ph++; grid_barrier(ph);
        epi_slstm(1, thr1, g_partA, b_ih1, b_hh1);
        if (t + 1 < T_STEPS) lif_phase(t + 1, thrL);
        ph++; grid_barrier(ph);
        gemm_phase<K2S>(g_S2 + split * (K2S * 128), w2d, spartB, sbuf, warp, lane);
        ph++; grid_barrier(ph);
        epi_slstm(2, thr2, g_partB, b_ih2, b_hh2);
        // no 4th barrier: ping-pong partials; epi2's mem2 writes are ordered
        // before next gemm2 by the two intervening barriers.
    }
}

// ---------------- heads ----------------
__global__ void heads_kernel(const float* __restrict__ wg, const float* __restrict__ bg,
                             const float* __restrict__ wd1, const float* __restrict__ bd1,
                             const float* __restrict__ wd2, const float* __restrict__ bd2,
                             const float* __restrict__ thr_dom_p, float* __restrict__ out)
{
    __shared__ float feat[512];
    __shared__ float sd[64];
    int b = blockIdx.x, tid = threadIdx.x;
    const float thr = *thr_dom_p;
#pragma unroll
    for (int j = 0; j < 4; j++)
        feat[tid + j * 128] = g_acc2[(tid + j * 128) * 128 + b] * (1.f / 400.f);
    __syncthreads();
    if (tid < 8) {
        float acc = bg[tid];
        for (int h = 0; h < 512; h++) acc = fmaf(feat[h], wg[tid * 512 + h], acc);
        out[b * 8 + tid] = acc;
    }
    if (tid < 64) {
        float acc = bd1[tid];
        for (int h = 0; h < 512; h++) acc = fmaf(feat[h], wd1[tid * 512 + h], acc);
        sd[tid] = (acc - thr > 0.f) ? 1.f : 0.f;
    }
    __syncthreads();
    if (tid < 10) {
        float acc = bd2[tid];
        for (int k = 0; k < 64; k++) acc = fmaf(sd[k], wd2[tid * 64 + k], acc);
        out[128 * 8 + b * 10 + tid] = acc;
    }
}

extern "C" void kernel_launch(void* const* d_in, const int* in_sizes, int n_in,
                              void* d_out, int out_size) {
    const float* x       = (const float*)d_in[0];
    const float* conv_w  = (const float*)d_in[1];
    const float* bn_g    = (const float*)d_in[2];
    const float* bn_b    = (const float*)d_in[3];
    const float* w_ih1   = (const float*)d_in[4];
    const float* w_hh1   = (const float*)d_in[5];
    const float* b_ih1   = (const float*)d_in[6];
    const float* b_hh1   = (const float*)d_in[7];
    const float* w_ih2   = (const float*)d_in[8];
    const float* w_hh2   = (const float*)d_in[9];
    const float* b_ih2   = (const float*)d_in[10];
    const float* b_hh2   = (const float*)d_in[11];
    const float* wg      = (const float*)d_in[12];
    const float* bg      = (const float*)d_in[13];
    const float* wd1     = (const float*)d_in[14];
    const float* bd1     = (const float*)d_in[15];
    const float* wd2     = (const float*)d_in[16];
    const float* bd2     = (const float*)d_in[17];
    const float* thrL    = (const float*)d_in[18];
    const float* thr1    = (const float*)d_in[19];
    const float* thr2    = (const float*)d_in[20];
    const float* thrD    = (const float*)d_in[21];

    const int SMEM_SCAN = 73728 + 131072 + 16384;   // 221184 B
    cudaFuncSetAttribute(scan_kernel, cudaFuncAttributeMaxDynamicSharedMemorySize, SMEM_SCAN);

    conv_kernel<<<T_STEPS, 128>>>(x, conv_w);
    stats_kernel<<<OC, 256>>>(bn_g, bn_b);
    norm_kernel<<<(OC * T_STEPS * BATCH + 255) / 256, 256>>>();
    scan_kernel<<<128, 512, SMEM_SCAN>>>(w_ih1, w_hh1, b_ih1, b_hh1,
                                         w_ih2, w_hh2, b_ih2, b_hh2,
                                         thrL, thr1, thr2);
    heads_kernel<<<128, 128>>>(wg, bg, wd1, bd1, wd2, bd2, thrD, (float*)d_out);
}